// round 15
// baseline (speedup 1.0000x reference)
#include <cuda_runtime.h>

// LSTM: B=2048, T=512, I=1, H=64, gates=256 (i,f,g,o), O=1. fp32 throughout.
// Grid: 296 CTAs x 128 threads = exactly 2 CTAs per SM (one balanced wave).
// Each CTA owns RPB=7 batch rows for the full T=512 recurrence.
//
// Cell-aligned gate ownership (R10/R14 winner): warp w covers cells
// m in [16w, 16w+16): lane l<16 owns (i,g) of cell m, lane l>=16 owns (f,o).
// (f,o) reach the (i,g) lane via two shfl.xor(16); h double-buffered in SMEM
// -> ONE __syncthreads per step. Activations via single MUFU.TANH with the
// sigmoid 1/2 pre-folded into register weights (R14 win).
//
// NEW this round: ROW-STAGGERED step body. The dot loop is row-outer: row r's
// 64 FFMA2 (4 independent chains) complete, then row r's activation / shfl /
// c-update / h-store run immediately — in the same basic block as rows
// r+1..6's FFMA2s, so the MUFU(16)/shfl(26) latency hides under remaining
// fma work instead of draining the pipe at end-of-step. x-contributions are
// hoisted to the step top. Target: kill the ~1000 cyc/step tail seen in R14
// (fma 62.4%, issue 46.5%).

#define BATCH  2048
#define TSTEPS 512
#define HID    64
#define RPB    7
#define NTHR   128
#define GRID   296   // 2 x 148 SMs; 296*7 = 2072 >= 2048 (tail clamped)

typedef unsigned long long u64;

__device__ __forceinline__ void fma2(u64 &acc, u64 a, u64 b) {
    asm("fma.rn.f32x2 %0, %1, %2, %0;" : "+l"(acc) : "l"(a), "l"(b));
}

__device__ __forceinline__ float2 unpack2(u64 v) {
    float2 r;
    asm("mov.b64 {%0, %1}, %2;" : "=f"(r.x), "=f"(r.y) : "l"(v));
    return r;
}

__device__ __forceinline__ u64 pack2(float lo, float hi) {
    u64 v;
    asm("mov.b64 %0, {%1, %2};" : "=l"(v) : "f"(lo), "f"(hi));
    return v;
}

// Hardware tanh (MUFU.TANH, sm_75+). Single op, lat ~16, abs err ~2^-11.
__device__ __forceinline__ float tanh_hw(float x) {
    float r;
    asm("tanh.approx.f32 %0, %1;" : "=f"(r) : "f"(x));
    return r;
}

// Scale both packed floats of a u64 by s.
__device__ __forceinline__ u64 scale2(u64 v, float s) {
    float2 p = unpack2(v);
    return pack2(p.x * s, p.y * s);
}

__global__ __launch_bounds__(NTHR, 2)
void lstm_fused_kernel(const float* __restrict__ x,      // [B, T, 1]
                       const float* __restrict__ w_ih,   // [256, 1]
                       const float* __restrict__ w_hh,   // [256, 64]
                       const float* __restrict__ b_ih,   // [256]
                       const float* __restrict__ b_hh,   // [256]
                       const float* __restrict__ w_lin,  // [1, 64]
                       const float* __restrict__ b_lin,  // [1]
                       float* __restrict__ out)          // [B, 1]
{
    __shared__ float sh_x[RPB * TSTEPS];      // 14 KB
    __shared__ float sh_h[2][RPB][HID];       // 3.5 KB, double-buffered

    const int t  = threadIdx.x;
    const int l  = t & 31;
    const int w  = t >> 5;
    const int b0 = blockIdx.x * RPB;

    const int  m  = (w << 4) + (l & 15);      // cell this thread serves
    const bool hi = (l & 16) != 0;            // upper half-warp = (f,o) owner
    const int  jA = m + (hi ? 64 : 0);        // i-row (lo) / f-row (hi)
    const int  jB = jA + 128;                 // g-row (lo) / o-row (hi)

    // Gate A (i or f) is always sigmoid -> pre-scale weights by 0.5.
    // Gate B: g (lo) is tanh -> no scale; o (hi) is sigmoid -> 0.5.
    const float sB = hi ? 0.5f : 1.0f;

    // ---- W_hh rows into registers as k-pairs (64 x u64 = 128 regs) ----
    u64 wA[HID / 2], wB[HID / 2];
    {
        const u64* w64 = reinterpret_cast<const u64*>(w_hh);
        const u64* pa = w64 + (size_t)jA * (HID / 2);
        const u64* pb = w64 + (size_t)jB * (HID / 2);
#pragma unroll
        for (int k = 0; k < HID / 2; ++k) {
            wA[k] = scale2(pa[k], 0.5f);
            wB[k] = scale2(pb[k], sB);
        }
    }

    const float wihA  = 0.5f * w_ih[jA];
    const float wihB  = sB   * w_ih[jB];
    const float biasA = 0.5f * (b_ih[jA] + b_hh[jA]);
    const float biasB = sB   * (b_ih[jB] + b_hh[jB]);

    // Branchless post-tanh affine: act = Ac * tanh(pre) + Cc
    const float AcB = hi ? 0.5f : 1.0f;
    const float CcB = hi ? 0.5f : 0.0f;

    // ---- stage x: 7 rows x 512 steps = 896 float4, clamp row for tail CTA ----
    {
        const float4* src = reinterpret_cast<const float4*>(x);
        float4* dst = reinterpret_cast<float4*>(sh_x);
#pragma unroll
        for (int i = 0; i < (RPB * TSTEPS / 4) / NTHR; ++i) {   // 7 iters
            int idx = t + i * NTHR;            // [0, 896)
            int rl  = idx >> 7;                // 128 float4 per row
            int g   = b0 + rl;
            if (g > BATCH - 1) g = BATCH - 1;  // clamp (garbage rows unused)
            dst[idx] = src[(size_t)g * (TSTEPS / 4) + (idx & 127)];
        }
    }
    // init h buffer 0 = 0
#pragma unroll
    for (int i = t; i < RPB * HID; i += NTHR)
        (&sh_h[0][0][0])[i] = 0.0f;

    float c[RPB];
#pragma unroll
    for (int r = 0; r < RPB; ++r) c[r] = 0.0f;

    __syncthreads();

    for (int step = 0; step < TSTEPS; ++step) {
        const int rb = step & 1;               // read buffer
        const int wb = rb ^ 1;                 // write buffer

        // ---- x contributions first (independent of h, off critical path) ----
        float xcA[RPB], xcB[RPB];
#pragma unroll
        for (int r = 0; r < RPB; ++r) {
            float xv = sh_x[r * TSTEPS + step];
            xcA[r] = fmaf(xv, wihA, biasA);
            xcB[r] = fmaf(xv, wihB, biasB);
        }

        // ---- row-staggered: dot(row r) then immediately epilogue(row r).
        //      Rows r+1.. provide FFMA2s to hide row r's MUFU/shfl latency. ----
#pragma unroll
        for (int r = 0; r < RPB; ++r) {
            const ulonglong2* hp =
                reinterpret_cast<const ulonglong2*>(&sh_h[rb][r][0]);

            // 4 independent accumulator chains (2 per gate), 16 LDS.128
            u64 aA0 = 0ull, aA1 = 0ull, aB0 = 0ull, aB1 = 0ull;
#pragma unroll
            for (int kk = 0; kk < HID / 8; ++kk) {   // 8 iters, 2 x LDS.128
                ulonglong2 h0 = hp[2 * kk];
                ulonglong2 h1 = hp[2 * kk + 1];
                fma2(aA0, h0.x, wA[4 * kk]);
                fma2(aA1, h0.y, wA[4 * kk + 1]);
                fma2(aB0, h0.x, wB[4 * kk]);
                fma2(aB1, h0.y, wB[4 * kk + 1]);
                fma2(aA0, h1.x, wA[4 * kk + 2]);
                fma2(aA1, h1.y, wA[4 * kk + 3]);
                fma2(aB0, h1.x, wB[4 * kk + 2]);
                fma2(aB1, h1.y, wB[4 * kk + 3]);
            }

            // ---- epilogue for row r (overlaps rows r+1.. dots) ----
            float2 pa0 = unpack2(aA0), pa1 = unpack2(aA1);
            float2 pb0 = unpack2(aB0), pb1 = unpack2(aB1);
            float preA = ((pa0.x + pa0.y) + (pa1.x + pa1.y)) + xcA[r];
            float preB = ((pb0.x + pb0.y) + (pb1.x + pb1.y)) + xcB[r];
            float actA = fmaf(0.5f, tanh_hw(preA), 0.5f);        // sigmoid(i/f)
            float actB = fmaf(AcB, tanh_hw(preB), CcB);          // tanh(g)/sig(o)

            float fv = __shfl_xor_sync(0xFFFFFFFFu, actA, 16);   // f for lo
            float ov = __shfl_xor_sync(0xFFFFFFFFu, actB, 16);   // o for lo
            c[r] = fmaf(fv, c[r], actA * actB);                  // f*c + i*g
            float hval = ov * tanh_hw(c[r]);
            if (!hi) sh_h[wb][r][m] = hval;        // one owner per (r, m)
        }
        __syncthreads();
    }

    // ---------- output projection: out[b] = h_last . w_lin + b_lin ----------
    // Last write went to buffer wb = (511 & 1) ^ 1 = 0.
    if (t < RPB && (b0 + t) < BATCH) {
        float s = b_lin[0];
#pragma unroll
        for (int k = 0; k < HID; ++k)
            s = fmaf(sh_h[0][t][k], w_lin[k], s);
        out[b0 + t] = s;
    }
}

extern "C" void kernel_launch(void* const* d_in, const int* in_sizes, int n_in,
                              void* d_out, int out_size) {
    const float* x     = (const float*)d_in[0];
    const float* w_ih  = (const float*)d_in[1];
    const float* w_hh  = (const float*)d_in[2];
    const float* b_ih  = (const float*)d_in[3];
    const float* b_hh  = (const float*)d_in[4];
    const float* w_lin = (const float*)d_in[5];
    const float* b_lin = (const float*)d_in[6];
    float* out = (float*)d_out;

    lstm_fused_kernel<<<GRID, NTHR>>>(x, w_ih, w_hh, b_ih, b_hh,
                                      w_lin, b_lin, out);
}